// round 11
// baseline (speedup 1.0000x reference)
#include <cuda_runtime.h>

// actions: [B=4096, T=256, A=64] fp32
// out[b,t,a] = x[b,0,a] + sum_{s=1..t} clip(x[b,s,a]-x[b,s-1,a], -0.5, 0.5)
//
// Persistent-CTA version of the best-known block scan (R9: ncu 77.2us):
//   Exactly 2*148=296 resident blocks; each grid-strides over b-rows so the
//   load pipeline never drains for block dispatch/wave transitions.
//   Per row: 256 thr = 16 t-segments x 16 a4-cols, SEGLEN=16, ONE barrier,
//   double-buffered smem (buffer reuse is two barriers apart -> safe).
//   __ldcg reads (no reuse, skip L1), __stwt writes (no L2 dirty residency).

#define A4     16   // float4 per A-dim
#define SEGS   16
#define SEGLEN 16
#define TSTEPS 256
#define NROWS  4096
#define NBLOCKS 296  // 148 SMs x 2 resident blocks

__device__ __forceinline__ float clip05(float d) {
    return fminf(fmaxf(d, -0.5f), 0.5f);
}

__device__ __forceinline__ float4 f4add(float4 a, float4 b) {
    return make_float4(a.x + b.x, a.y + b.y, a.z + b.z, a.w + b.w);
}

__global__ void __launch_bounds__(256, 2) smoothness_persist_kernel(
    const float4* __restrict__ x, float4* __restrict__ y)
{
    const int tid = threadIdx.x;
    const int seg = tid >> 4;     // 0..15
    const int a4  = tid & 15;     // 0..15
    const int t0  = seg * SEGLEN;

    __shared__ float4 s_sum[2][SEGS][A4];  // per-segment totals, double-buffered
    __shared__ float4 s_x0[2][A4];         // x[b,0,:], double-buffered

    int buf = 0;
    for (int b = blockIdx.x; b < NROWS; b += NBLOCKS, buf ^= 1) {
        const float4* xb = x + (long)b * (TSTEPS * A4);
        float4*       yb = y + (long)b * (TSTEPS * A4);

        // Boundary load first (first value consumed), then the batch.
        float4 prev;
        if (seg > 0)
            prev = __ldcg(&xb[(t0 - 1) * A4 + a4]);

        float4 c[SEGLEN];
        #pragma unroll
        for (int j = 0; j < SEGLEN; ++j)
            c[j] = __ldcg(&xb[(t0 + j) * A4 + a4]);

        // Local prefix of clipped diffs, in-place into c[].
        float4 acc = make_float4(0.f, 0.f, 0.f, 0.f);
        int jstart = 0;
        if (seg == 0) {
            s_x0[buf][a4] = c[0];
            prev = c[0];
            c[0] = acc;                   // local prefix at t=0 is 0
            jstart = 1;
        }
        #pragma unroll
        for (int j = 0; j < SEGLEN; ++j) {
            if (j < jstart) continue;
            float4 cur = c[j];
            acc.x += clip05(cur.x - prev.x);
            acc.y += clip05(cur.y - prev.y);
            acc.z += clip05(cur.z - prev.z);
            acc.w += clip05(cur.w - prev.w);
            prev = cur;
            c[j] = acc;
        }
        s_sum[buf][seg][a4] = acc;
        __syncthreads();                  // one barrier per row

        // Exclusive prefix over segment totals + base x[b,0,:].
        float4 offset = s_x0[buf][a4];
        #pragma unroll
        for (int k = 0; k < SEGS; ++k) {
            if (k < seg) offset = f4add(offset, s_sum[buf][k][a4]);
        }

        // Add offset and store write-through.
        #pragma unroll
        for (int j = 0; j < SEGLEN; ++j)
            __stwt(&yb[(t0 + j) * A4 + a4], f4add(offset, c[j]));
    }
}

extern "C" void kernel_launch(void* const* d_in, const int* in_sizes, int n_in,
                              void* d_out, int out_size) {
    const float4* x = (const float4*)d_in[0];
    float4* y = (float4*)d_out;
    smoothness_persist_kernel<<<NBLOCKS, 256>>>(x, y);
}

// round 14
// speedup vs baseline: 1.1444x; 1.1444x over previous
#include <cuda_runtime.h>

// actions: [B=4096, T=256, A=64] fp32
// out[b,t,a] = x[b,0,a] + sum_{s=1..t} clip(x[b,s,a]-x[b,s-1,a], -0.5, 0.5)
//
// FINAL (best measured kernel clock: 77.2us ncu, 6.22 TB/s, DRAM 78.5%):
//   1 block per b-row (grid=4096), 256 thr = 16 t-segments x 16 a4-cols,
//   SEGLEN=16, single __syncthreads.
//   - boundary load hoisted first (consumed first in the prefix loop)
//   - __ldcg reads (zero reuse -> skip L1 insertion)
//   - __stwt writes (write-through; no L2 dirty residency for the
//     never-re-read output stream)
// Tested and rejected: higher occupancy (R3, neutral), evict-first __ldcs
// (R4, neutral), barrier-free warp shuffle scan (R7, worse coalescing),
// persistent CTAs (R11, serializes what HW dispatch overlaps).

#define A4     16   // float4 per A-dim
#define SEGS   16
#define SEGLEN 16
#define TSTEPS 256

__device__ __forceinline__ float clip05(float d) {
    return fminf(fmaxf(d, -0.5f), 0.5f);
}

__device__ __forceinline__ float4 f4add(float4 a, float4 b) {
    return make_float4(a.x + b.x, a.y + b.y, a.z + b.z, a.w + b.w);
}

__global__ void __launch_bounds__(256, 2) smoothness_scan_kernel(
    const float4* __restrict__ x, float4* __restrict__ y)
{
    const int b   = blockIdx.x;
    const int tid = threadIdx.x;
    const int seg = tid >> 4;     // 0..15
    const int a4  = tid & 15;     // 0..15

    const float4* xb = x + (long)b * (TSTEPS * A4);
    float4*       yb = y + (long)b * (TSTEPS * A4);

    __shared__ float4 s_sum[SEGS][A4];   // per-segment clipped-diff totals
    __shared__ float4 s_x0[A4];          // x[b, 0, :]

    const int t0 = seg * SEGLEN;

    // Boundary load FIRST (it is the first value consumed), then the batch.
    float4 prev;
    if (seg > 0)
        prev = __ldcg(&xb[(t0 - 1) * A4 + a4]);   // L2-hit re-read

    float4 c[SEGLEN];
    #pragma unroll
    for (int j = 0; j < SEGLEN; ++j)
        c[j] = __ldcg(&xb[(t0 + j) * A4 + a4]);

    // Local prefix of clipped diffs within the segment, in-place into c[].
    float4 acc = make_float4(0.f, 0.f, 0.f, 0.f);
    int jstart = 0;
    if (seg == 0) {
        s_x0[a4] = c[0];
        prev = c[0];
        c[0] = acc;                      // local prefix at t=0 is 0
        jstart = 1;
    }
    #pragma unroll
    for (int j = 0; j < SEGLEN; ++j) {
        if (j < jstart) continue;
        float4 cur = c[j];
        acc.x += clip05(cur.x - prev.x);
        acc.y += clip05(cur.y - prev.y);
        acc.z += clip05(cur.z - prev.z);
        acc.w += clip05(cur.w - prev.w);
        prev = cur;
        c[j] = acc;
    }
    s_sum[seg][a4] = acc;
    __syncthreads();                     // single barrier

    // Exclusive prefix over segment totals + base x[b,0,:].
    float4 offset = s_x0[a4];
    #pragma unroll
    for (int k = 0; k < SEGS; ++k) {
        if (k < seg) offset = f4add(offset, s_sum[k][a4]);
    }

    // Add offset and store write-through.
    #pragma unroll
    for (int j = 0; j < SEGLEN; ++j)
        __stwt(&yb[(t0 + j) * A4 + a4], f4add(offset, c[j]));
}

extern "C" void kernel_launch(void* const* d_in, const int* in_sizes, int n_in,
                              void* d_out, int out_size) {
    const float4* x = (const float4*)d_in[0];
    float4* y = (float4*)d_out;
    smoothness_scan_kernel<<<4096, 256>>>(x, y);
}

// round 15
// speedup vs baseline: 1.1498x; 1.0047x over previous
#include <cuda_runtime.h>

// actions: [B=4096, T=256, A=64] fp32
// out[b,t,a] = x[b,0,a] + sum_{s=1..t} clip(x[b,s,a]-x[b,s-1,a], -0.5, 0.5)
//
// FINAL — verified best (bench 82.43us; ncu 77.2-77.9us, 6.2 TB/s, DRAM 78%):
//   1 block per b-row (grid=4096), 256 thr = 16 t-segments x 16 a4-cols,
//   SEGLEN=16, single __syncthreads.
//   - boundary load hoisted first (consumed first in the prefix loop)
//   - __ldcg reads (zero reuse -> skip L1 insertion)
//   - __stwt writes (write-through; no L2 dirty residency for the
//     never-re-read output stream)
// Tested and rejected with metric evidence: higher occupancy (R3, neutral),
// evict-first __ldcs (R4, neutral), barrier-free warp shuffle scan (R7,
// worse coalescing), persistent CTAs (R11, serializes HW-overlapped
// dispatch). Memory floor: 512 MiB @ 8 TB/s = 64us; this kernel runs at
// ~82% of that floor, near the practical mixed-R/W HBM ceiling.

#define A4     16   // float4 per A-dim
#define SEGS   16
#define SEGLEN 16
#define TSTEPS 256

__device__ __forceinline__ float clip05(float d) {
    return fminf(fmaxf(d, -0.5f), 0.5f);
}

__device__ __forceinline__ float4 f4add(float4 a, float4 b) {
    return make_float4(a.x + b.x, a.y + b.y, a.z + b.z, a.w + b.w);
}

__global__ void __launch_bounds__(256, 2) smoothness_scan_kernel(
    const float4* __restrict__ x, float4* __restrict__ y)
{
    const int b   = blockIdx.x;
    const int tid = threadIdx.x;
    const int seg = tid >> 4;     // 0..15
    const int a4  = tid & 15;     // 0..15

    const float4* xb = x + (long)b * (TSTEPS * A4);
    float4*       yb = y + (long)b * (TSTEPS * A4);

    __shared__ float4 s_sum[SEGS][A4];   // per-segment clipped-diff totals
    __shared__ float4 s_x0[A4];          // x[b, 0, :]

    const int t0 = seg * SEGLEN;

    // Boundary load FIRST (it is the first value consumed), then the batch.
    float4 prev;
    if (seg > 0)
        prev = __ldcg(&xb[(t0 - 1) * A4 + a4]);   // L2-hit re-read

    float4 c[SEGLEN];
    #pragma unroll
    for (int j = 0; j < SEGLEN; ++j)
        c[j] = __ldcg(&xb[(t0 + j) * A4 + a4]);

    // Local prefix of clipped diffs within the segment, in-place into c[].
    float4 acc = make_float4(0.f, 0.f, 0.f, 0.f);
    int jstart = 0;
    if (seg == 0) {
        s_x0[a4] = c[0];
        prev = c[0];
        c[0] = acc;                      // local prefix at t=0 is 0
        jstart = 1;
    }
    #pragma unroll
    for (int j = 0; j < SEGLEN; ++j) {
        if (j < jstart) continue;
        float4 cur = c[j];
        acc.x += clip05(cur.x - prev.x);
        acc.y += clip05(cur.y - prev.y);
        acc.z += clip05(cur.z - prev.z);
        acc.w += clip05(cur.w - prev.w);
        prev = cur;
        c[j] = acc;
    }
    s_sum[seg][a4] = acc;
    __syncthreads();                     // single barrier

    // Exclusive prefix over segment totals + base x[b,0,:].
    float4 offset = s_x0[a4];
    #pragma unroll
    for (int k = 0; k < SEGS; ++k) {
        if (k < seg) offset = f4add(offset, s_sum[k][a4]);
    }

    // Add offset and store write-through.
    #pragma unroll
    for (int j = 0; j < SEGLEN; ++j)
        __stwt(&yb[(t0 + j) * A4 + a4], f4add(offset, c[j]));
}

extern "C" void kernel_launch(void* const* d_in, const int* in_sizes, int n_in,
                              void* d_out, int out_size) {
    const float4* x = (const float4*)d_in[0];
    float4* y = (float4*)d_out;
    smoothness_scan_kernel<<<4096, 256>>>(x, y);
}